// round 3
// baseline (speedup 1.0000x reference)
#include <cuda_runtime.h>
#include <cuda_bf16.h>

#define BB    256
#define TT    512
#define FF    64
#define UU    256
#define G4    1024
#define KC    320      // 5*FF im2col width
#define OUTS  64
#define OD    8

// ---------------- device scratch (no allocations allowed) ----------------
__device__ float g_xcol[(size_t)BB * TT * KC];
__device__ float g_ya  [(size_t)BB * TT * UU];
__device__ float g_yb  [(size_t)BB * TT * UU];
__device__ float g_xw  [(size_t)BB * TT * G4];
__device__ float g_hbuf[2][BB * UU];
__device__ float g_hfin[BB * UU];
__device__ float g_cfin[BB * UU];
__device__ float g_hdec[(size_t)BB * OUTS * UU];
__device__ float g_wc  [UU * G4];
__device__ unsigned g_cnt_l[16 * 32];   // per-group counters, padded 128B apart
__device__ unsigned g_cnt_g;
__device__ unsigned g_gen;

// ---------------- helpers ----------------
__device__ __forceinline__ float sigm_f(float x) {
    return __fdividef(1.0f, 1.0f + __expf(-x));
}
__device__ __forceinline__ float tanh_f(float x) {
    float xc = fminf(fmaxf(x, -15.0f), 15.0f);
    float e  = __expf(-2.0f * xc);
    return __fdividef(1.0f - e, 1.0f + e);
}

// Two-level grid barrier: 16 blocks/group -> 16 groups. Generation counter is
// monotone across launches/replays; counters always return to 0 (deterministic).
__device__ __forceinline__ void grid_sync_256() {
    __syncthreads();
    if (threadIdx.x == 0) {
        __threadfence();
        unsigned gen = *((volatile unsigned*)&g_gen);
        if (atomicAdd(&g_cnt_l[blockIdx.x * 32], 1u) == 15u) {
            if (atomicAdd(&g_cnt_g, 1u) == 15u) {
                for (int i = 0; i < 16; i++)
                    *((volatile unsigned*)&g_cnt_l[i * 32]) = 0u;
                *((volatile unsigned*)&g_cnt_g) = 0u;
                __threadfence();
                *((volatile unsigned*)&g_gen) = gen + 1u;
            }
        }
        while (*((volatile unsigned*)&g_gen) == gen) { __nanosleep(64); }
        __threadfence();
    }
    __syncthreads();
}

// ---------------- im2col (SAME pad, kernel 5) ----------------
__global__ void im2col_kernel(const float* __restrict__ x) {
    int idx = blockIdx.x * 256 + threadIdx.x;
    int col = idx % KC;
    int t   = (idx / KC) % TT;
    int b   = idx / (KC * TT);
    int k   = col >> 6;
    int f   = col & 63;
    int tt  = t + k - 2;
    g_xcol[idx] = (tt >= 0 && tt < TT) ? x[((size_t)b * TT + tt) * FF + f] : 0.0f;
}

// ---------------- fp32 tiled GEMM: C = A[M,K] @ W[K,N] + bias ----------------
template<int RELU>
__global__ __launch_bounds__(256)
void gemm_bias_kernel(const float* __restrict__ A, const float* __restrict__ W,
                      const float* __restrict__ bias, float* __restrict__ C,
                      int M, int N, int K)
{
    __shared__ float As[16][68];
    __shared__ float Bs[16][64];
    const int tid = threadIdx.x;
    const int m0 = blockIdx.x * 64;
    const int n0 = blockIdx.y * 64;
    const int tm = tid >> 4, tn = tid & 15;
    const int a_row = tid >> 2,  a_col = (tid & 3) << 2;
    const int b_row = tid >> 4,  b_col = (tid & 15) << 2;

    const float* Ap = A + (size_t)(m0 + a_row) * K + a_col;
    const float* Wp = W + (size_t)b_row * N + (n0 + b_col);

    float acc[4][4];
#pragma unroll
    for (int i = 0; i < 4; i++)
#pragma unroll
        for (int j = 0; j < 4; j++) acc[i][j] = 0.0f;

    for (int k0 = 0; k0 < K; k0 += 16) {
        float4 av = *(const float4*)(Ap + k0);
        float4 wv = *(const float4*)(Wp + (size_t)k0 * N);
        As[a_col + 0][a_row] = av.x;
        As[a_col + 1][a_row] = av.y;
        As[a_col + 2][a_row] = av.z;
        As[a_col + 3][a_row] = av.w;
        *(float4*)&Bs[b_row][b_col] = wv;
        __syncthreads();
#pragma unroll
        for (int kk = 0; kk < 16; kk++) {
            float4 a4 = *(const float4*)&As[kk][tm << 2];
            float4 b4 = *(const float4*)&Bs[kk][tn << 2];
            acc[0][0] += a4.x * b4.x; acc[0][1] += a4.x * b4.y;
            acc[0][2] += a4.x * b4.z; acc[0][3] += a4.x * b4.w;
            acc[1][0] += a4.y * b4.x; acc[1][1] += a4.y * b4.y;
            acc[1][2] += a4.y * b4.z; acc[1][3] += a4.y * b4.w;
            acc[2][0] += a4.z * b4.x; acc[2][1] += a4.z * b4.y;
            acc[2][2] += a4.z * b4.z; acc[2][3] += a4.z * b4.w;
            acc[3][0] += a4.w * b4.x; acc[3][1] += a4.w * b4.y;
            acc[3][2] += a4.w * b4.z; acc[3][3] += a4.w * b4.w;
        }
        __syncthreads();
    }

    float4 bv = *(const float4*)&bias[n0 + (tn << 2)];
#pragma unroll
    for (int i = 0; i < 4; i++) {
        float4 o;
        o.x = acc[i][0] + bv.x; o.y = acc[i][1] + bv.y;
        o.z = acc[i][2] + bv.z; o.w = acc[i][3] + bv.w;
        if (RELU) {
            o.x = fmaxf(o.x, 0.0f); o.y = fmaxf(o.y, 0.0f);
            o.z = fmaxf(o.z, 0.0f); o.w = fmaxf(o.w, 0.0f);
        }
        *(float4*)&C[(size_t)(m0 + (tm << 2) + i) * N + n0 + (tn << 2)] = o;
    }
}

// ---------------- persistent LSTM scan ----------------
// grid (16,16): blockIdx.x = batch tile (16 rows), blockIdx.y = unit tile
// (16 units -> 64 gate columns). U tile resident in smem for the whole scan,
// c in registers, h ping-ponged through g_hbuf with one grid barrier/step.
__global__ __launch_bounds__(256, 2)
void lstm_scan(const float* __restrict__ xw,   // [B][Tlen][1024] or nullptr
               const float* __restrict__ bias, // [1024] (used when xw==null)
               const float* __restrict__ Umat, // [256][1024]
               float* __restrict__ yout,       // [B][Tlen][256]
               int Tlen, int initFromState)
{
    extern __shared__ float sm[];
    float* U_s = sm;           // 16384 floats
    float* h_s = sm + 16384;   //  4096 floats
    float* z_s = sm + 20480;   //  1024 floats

    const int tid = threadIdx.x;
    const int b0  = blockIdx.x * 16;
    const int u0  = blockIdx.y * 16;

    // U tile, gate-major local layout: U_s[k*64 + g*16 + i]
    for (int idx = tid; idx < 16384; idx += 256) {
        int k = idx >> 6, c = idx & 63;
        U_s[idx] = Umat[k * G4 + (c >> 4) * UU + u0 + (c & 15)];
    }

    const int b_l = tid >> 4, u_l = tid & 15;
    const int gidx = (b0 + b_l) * UU + u0 + u_l;
    float c_reg = initFromState ? g_cfin[gidx] : 0.0f;
    g_hbuf[0][gidx] = initFromState ? g_hfin[gidx] : 0.0f;

    const int jj  = tid & 31;        // column pair 0..31
    const int bq  = tid >> 5;        // row pair 0..7
    const int j0  = jj << 1;
    const int bl0 = bq << 1;
    const int jglob0 = (j0 >> 4) * UU + u0 + (j0 & 15);

    grid_sync_256();

    for (int t = 0; t < Tlen; t++) {
        // additive term (xw row or bias)
        float a00, a01, a10, a11;
        if (xw) {
            float2 x0 = *(const float2*)(xw + ((size_t)(b0 + bl0) * Tlen + t) * G4 + jglob0);
            float2 x1 = *(const float2*)(xw + ((size_t)(b0 + bl0 + 1) * Tlen + t) * G4 + jglob0);
            a00 = x0.x; a01 = x0.y; a10 = x1.x; a11 = x1.y;
        } else {
            float2 bv = *(const float2*)&bias[jglob0];
            a00 = bv.x; a01 = bv.y; a10 = bv.x; a11 = bv.y;
        }

        // stage h rows for this step (bypass L1: written by other SMs)
        {
            const float4* src = (const float4*)(g_hbuf[t & 1] + b0 * UU);
            float4* dst = (float4*)h_s;
#pragma unroll
            for (int r = 0; r < 4; r++)
                dst[tid + r * 256] = __ldcg(src + tid + r * 256);
        }
        __syncthreads();

        // z = add + h @ U   (2 rows x 2 cols per thread)
        const float* hr0 = h_s + bl0 * 256;
        const float* hr1 = hr0 + 256;
        const float2* Uv = (const float2*)U_s;
#pragma unroll 4
        for (int k = 0; k < 256; k += 4) {
            float4 h0 = *(const float4*)(hr0 + k);
            float4 h1 = *(const float4*)(hr1 + k);
            float2 u0v = Uv[(k + 0) * 32 + jj];
            float2 u1v = Uv[(k + 1) * 32 + jj];
            float2 u2v = Uv[(k + 2) * 32 + jj];
            float2 u3v = Uv[(k + 3) * 32 + jj];
            a00 += h0.x * u0v.x; a01 += h0.x * u0v.y;
            a10 += h1.x * u0v.x; a11 += h1.x * u0v.y;
            a00 += h0.y * u1v.x; a01 += h0.y * u1v.y;
            a10 += h1.y * u1v.x; a11 += h1.y * u1v.y;
            a00 += h0.z * u2v.x; a01 += h0.z * u2v.y;
            a10 += h1.z * u2v.x; a11 += h1.z * u2v.y;
            a00 += h0.w * u3v.x; a01 += h0.w * u3v.y;
            a10 += h1.w * u3v.x; a11 += h1.w * u3v.y;
        }
        *(float2*)&z_s[ bl0      * 64 + j0] = make_float2(a00, a01);
        *(float2*)&z_s[(bl0 + 1) * 64 + j0] = make_float2(a10, a11);
        __syncthreads();

        // gates: one (b,u) per thread
        {
            float zi = z_s[b_l * 64 +      u_l];
            float zf = z_s[b_l * 64 + 16 + u_l];
            float zg = z_s[b_l * 64 + 32 + u_l];
            float zo = z_s[b_l * 64 + 48 + u_l];
            float cn = sigm_f(zf) * c_reg + sigm_f(zi) * tanh_f(zg);
            float hn = sigm_f(zo) * tanh_f(cn);
            c_reg = cn;
            yout[((size_t)(b0 + b_l) * Tlen + t) * UU + u0 + u_l] = hn;
            g_hbuf[(t + 1) & 1][gidx] = hn;
            if (t == Tlen - 1) { g_hfin[gidx] = hn; g_cfin[gidx] = cn; }
        }
        grid_sync_256();
    }
}

// ---------------- combine decoder weights: wc = cell_w + cell_u ----------------
__global__ void combine_w_kernel(const float* __restrict__ a, const float* __restrict__ b) {
    int i = blockIdx.x * 256 + threadIdx.x;
    g_wc[i] = a[i] + b[i];
}

// ---------------- dense head: out[row,o] = h[row,:] @ dense_w + b ----------------
__global__ void dense_kernel(const float* __restrict__ h, const float* __restrict__ w,
                             const float* __restrict__ b, float* __restrict__ out) {
    __shared__ float ws[UU * OD];
    for (int i = threadIdx.x; i < UU * OD; i += 256) ws[i] = w[i];
    __syncthreads();
    int idx = blockIdx.x * 256 + threadIdx.x;   // 131072 total
    int o   = idx & 7;
    int row = idx >> 3;
    float acc = b[o];
    const float* hp = h + (size_t)row * UU;
#pragma unroll 8
    for (int k = 0; k < UU; k++) acc += hp[k] * ws[k * OD + o];
    out[idx] = acc;
}

// ---------------- launch ----------------
extern "C" void kernel_launch(void* const* d_in, const int* in_sizes, int n_in,
                              void* d_out, int out_size)
{
    const float* x     = (const float*)d_in[0];
    const float* cnn_w = (const float*)d_in[1];
    const float* cnn_b = (const float*)d_in[2];
    const float* ew0 = (const float*)d_in[3];
    const float* eu0 = (const float*)d_in[4];
    const float* eb0 = (const float*)d_in[5];
    const float* ew1 = (const float*)d_in[6];
    const float* eu1 = (const float*)d_in[7];
    const float* eb1 = (const float*)d_in[8];
    const float* ew2 = (const float*)d_in[9];
    const float* eu2 = (const float*)d_in[10];
    const float* eb2 = (const float*)d_in[11];
    const float* cw  = (const float*)d_in[12];
    const float* cu  = (const float*)d_in[13];
    const float* cb  = (const float*)d_in[14];
    const float* dw  = (const float*)d_in[15];
    const float* db  = (const float*)d_in[16];
    float* out = (float*)d_out;

    float *xcol, *ya, *yb, *xwp, *hdec, *wc;
    cudaGetSymbolAddress((void**)&xcol, g_xcol);
    cudaGetSymbolAddress((void**)&ya,   g_ya);
    cudaGetSymbolAddress((void**)&yb,   g_yb);
    cudaGetSymbolAddress((void**)&xwp,  g_xw);
    cudaGetSymbolAddress((void**)&hdec, g_hdec);
    cudaGetSymbolAddress((void**)&wc,   g_wc);

    const int SCAN_SMEM = 21504 * 4;   // 86016 B
    cudaFuncSetAttribute(lstm_scan, cudaFuncAttributeMaxDynamicSharedMemorySize, SCAN_SMEM);

    dim3 scan_grid(16, 16);
    const size_t M = (size_t)BB * TT;

    // conv: im2col + GEMM(+bias,ReLU)
    im2col_kernel<<<(BB * TT * KC) / 256, 256>>>(x);
    gemm_bias_kernel<1><<<dim3(M / 64, UU / 64), 256>>>(xcol, cnn_w, cnn_b, ya, (int)M, UU, KC);

    // encoder layer 0
    gemm_bias_kernel<0><<<dim3(M / 64, G4 / 64), 256>>>(ya, ew0, eb0, xwp, (int)M, G4, UU);
    lstm_scan<<<scan_grid, 256, SCAN_SMEM>>>(xwp, nullptr, eu0, yb, TT, 0);

    // encoder layer 1
    gemm_bias_kernel<0><<<dim3(M / 64, G4 / 64), 256>>>(yb, ew1, eb1, xwp, (int)M, G4, UU);
    lstm_scan<<<scan_grid, 256, SCAN_SMEM>>>(xwp, nullptr, eu1, ya, TT, 0);

    // encoder layer 2 (only final h,c needed; yout to yb is scratch)
    gemm_bias_kernel<0><<<dim3(M / 64, G4 / 64), 256>>>(ya, ew2, eb2, xwp, (int)M, G4, UU);
    lstm_scan<<<scan_grid, 256, SCAN_SMEM>>>(xwp, nullptr, eu2, yb, TT, 0);

    // decoder: z = h @ (cell_w + cell_u) + b, 64 steps from (h,c)
    combine_w_kernel<<<(UU * G4) / 256, 256>>>(cw, cu);
    lstm_scan<<<scan_grid, 256, SCAN_SMEM>>>(nullptr, cb, wc, hdec, OUTS, 1);

    // dense head
    dense_kernel<<<(BB * OUTS * OD) / 256, 256>>>(hdec, dw, db, out);
}

// round 5
// speedup vs baseline: 1.1695x; 1.1695x over previous
#include <cuda_runtime.h>
#include <cuda_bf16.h>
#include <cstdint>

#define BB    256
#define TT    512
#define FF    64
#define UU    256
#define G4    1024
#define KC    320
#define OUTS  64
#define OD    8
#define MTOT  (BB*TT)   // 131072

// ======================= device scratch =======================
__device__ __nv_bfloat16 g_xc_hi[(size_t)MTOT * KC];
__device__ __nv_bfloat16 g_xc_lo[(size_t)MTOT * KC];
__device__ __nv_bfloat16 g_a_hi [(size_t)MTOT * UU];
__device__ __nv_bfloat16 g_a_lo [(size_t)MTOT * UU];
__device__ __nv_bfloat16 g_wt_hi[G4 * UU];
__device__ __nv_bfloat16 g_wt_lo[G4 * UU];
__device__ __nv_bfloat16 g_cwt_hi[UU * KC];
__device__ __nv_bfloat16 g_cwt_lo[UU * KC];
__device__ float g_xw  [(size_t)MTOT * G4];
__device__ float g_hbuf[2][BB * UU];
__device__ float g_hfin[BB * UU];
__device__ float g_cfin[BB * UU];
__device__ float g_hdec[(size_t)BB * OUTS * UU];
__device__ float g_wc  [UU * G4];
__device__ unsigned g_cnt_l[16 * 32];
__device__ unsigned g_cnt_g;
__device__ unsigned g_gen;

// ======================= PTX helpers (base-target only) =======================
__device__ __forceinline__ uint32_t smem_u32(const void* p) {
    uint32_t a;
    asm("{ .reg .u64 t; cvta.to.shared.u64 t, %1; cvt.u32.u64 %0, t; }" : "=r"(a) : "l"(p));
    return a;
}
__device__ __forceinline__ void ldm_x4(uint32_t* r, uint32_t addr) {
    asm volatile("ldmatrix.sync.aligned.m8n8.x4.shared.b16 {%0,%1,%2,%3}, [%4];"
        : "=r"(r[0]), "=r"(r[1]), "=r"(r[2]), "=r"(r[3]) : "r"(addr));
}
__device__ __forceinline__ void mma16816(float* d, const uint32_t* a, const uint32_t* b) {
    asm volatile("mma.sync.aligned.m16n8k16.row.col.f32.bf16.bf16.f32 "
        "{%0,%1,%2,%3}, {%4,%5,%6,%7}, {%8,%9}, {%0,%1,%2,%3};"
        : "+f"(d[0]), "+f"(d[1]), "+f"(d[2]), "+f"(d[3])
        : "r"(a[0]), "r"(a[1]), "r"(a[2]), "r"(a[3]), "r"(b[0]), "r"(b[1]));
}

// ======================= misc helpers =======================
__device__ __forceinline__ float sigm_f(float x) {
    return __fdividef(1.0f, 1.0f + __expf(-x));
}
__device__ __forceinline__ float tanh_f(float x) {
    float xc = fminf(fmaxf(x, -15.0f), 15.0f);
    float e  = __expf(-2.0f * xc);
    return __fdividef(1.0f - e, 1.0f + e);
}
__device__ __forceinline__ void split_bf16(float v, __nv_bfloat16& h, __nv_bfloat16& l) {
    h = __float2bfloat16(v);
    l = __float2bfloat16(v - __bfloat162float(h));
}

__device__ __forceinline__ void grid_sync_256() {
    __syncthreads();
    if (threadIdx.x == 0) {
        __threadfence();
        unsigned gen = *((volatile unsigned*)&g_gen);
        if (atomicAdd(&g_cnt_l[blockIdx.x * 32], 1u) == 15u) {
            if (atomicAdd(&g_cnt_g, 1u) == 15u) {
                for (int i = 0; i < 16; i++)
                    *((volatile unsigned*)&g_cnt_l[i * 32]) = 0u;
                *((volatile unsigned*)&g_cnt_g) = 0u;
                __threadfence();
                *((volatile unsigned*)&g_gen) = gen + 1u;
            }
        }
        while (*((volatile unsigned*)&g_gen) == gen) { __nanosleep(64); }
        __threadfence();
    }
    __syncthreads();
}

// ======================= im2col + split =======================
__global__ void im2col_split(const float* __restrict__ x) {
    size_t idx = (size_t)blockIdx.x * 256 + threadIdx.x;
    int col = (int)(idx % KC);
    size_t mt = idx / KC;
    int t = (int)(mt % TT);
    int b = (int)(mt / TT);
    int k = col >> 6, f = col & 63;
    int tt = t + k - 2;
    float v = (tt >= 0 && tt < TT) ? x[((size_t)b * TT + tt) * FF + f] : 0.0f;
    __nv_bfloat16 h, l; split_bf16(v, h, l);
    g_xc_hi[idx] = h; g_xc_lo[idx] = l;
}

// W[K,N] -> Wt_hi/lo[N,K] bf16 (transpose + split)
__global__ void wsplit(const float* __restrict__ W, __nv_bfloat16* __restrict__ hi,
                       __nv_bfloat16* __restrict__ lo, int K, int N) {
    int idx = blockIdx.x * 256 + threadIdx.x;
    if (idx >= K * N) return;
    int n = idx / K, k = idx % K;
    float v = W[(size_t)k * N + n];
    __nv_bfloat16 h, l; split_bf16(v, h, l);
    hi[idx] = h; lo[idx] = l;
}

// ======================= HMMA split-bf16 GEMM =======================
// C[M,N] = (Ahi+Alo)[M,K] @ (Bhi+Blo)[N,K]^T + bias, passes hi*hi + hi*lo + lo*hi.
// grid (N/128, M/128), 256 threads = 8 warps (4 along M x 2 along N).
// OUTMODE 0: fp32 C; 1: split-bf16 Chi/Clo.
#define LDP 72           // padded row length (bf16) -> 144B rows, 16B aligned
#define TILE_ELE (128 * LDP)

template<int RELU, int OUTMODE>
__global__ __launch_bounds__(256)
void mma_gemm(const __nv_bfloat16* __restrict__ Ahi, const __nv_bfloat16* __restrict__ Alo,
              const __nv_bfloat16* __restrict__ Bhi, const __nv_bfloat16* __restrict__ Blo,
              const float* __restrict__ bias,
              float* __restrict__ C,
              __nv_bfloat16* __restrict__ Chi, __nv_bfloat16* __restrict__ Clo,
              int M, int N, int K)
{
    extern __shared__ __nv_bfloat16 smem[];
    __nv_bfloat16* As_h = smem;
    __nv_bfloat16* As_l = smem + TILE_ELE;
    __nv_bfloat16* Bs_h = smem + 2 * TILE_ELE;
    __nv_bfloat16* Bs_l = smem + 3 * TILE_ELE;

    const int tid  = threadIdx.x;
    const int lane = tid & 31;
    const int wid  = tid >> 5;
    const int wm   = wid & 3;    // 0..3, 32 rows each
    const int wn   = wid >> 2;   // 0..1, 64 cols each
    const int n0 = blockIdx.x * 128;
    const int m0 = blockIdx.y * 128;

    float acc[2][8][4];
#pragma unroll
    for (int i = 0; i < 2; i++)
#pragma unroll
        for (int j = 0; j < 8; j++)
#pragma unroll
            for (int q = 0; q < 4; q++) acc[i][j][q] = 0.0f;

    // ldmatrix source offsets (element units within a tile)
    const int ar = lane & 15, ac = (lane >> 4) << 3;                 // A map
    const int br = (lane & 7) + ((lane >> 4) << 3);                  // B map
    const int bc = ((lane >> 3) & 1) << 3;
    const uint32_t sA_h = smem_u32(As_h), sA_l = smem_u32(As_l);
    const uint32_t sB_h = smem_u32(Bs_h), sB_l = smem_u32(Bs_l);

    for (int k0 = 0; k0 < K; k0 += 64) {
        // stage 128x64 tiles (hi/lo for A and B)
#pragma unroll
        for (int r = 0; r < 4; r++) {
            int unit = tid + r * 256;            // 1024 units of 8 bf16
            int row = unit >> 3, c8 = (unit & 7) << 3;
            size_t ga = (size_t)(m0 + row) * K + k0 + c8;
            size_t gb = (size_t)(n0 + row) * K + k0 + c8;
            *(uint4*)&As_h[row * LDP + c8] = *(const uint4*)&Ahi[ga];
            *(uint4*)&As_l[row * LDP + c8] = *(const uint4*)&Alo[ga];
            *(uint4*)&Bs_h[row * LDP + c8] = *(const uint4*)&Bhi[gb];
            *(uint4*)&Bs_l[row * LDP + c8] = *(const uint4*)&Blo[gb];
        }
        __syncthreads();

#pragma unroll
        for (int kk = 0; kk < 4; kk++) {
            const int kof = kk * 16;
            uint32_t ah[2][4], al[2][4];
#pragma unroll
            for (int mf = 0; mf < 2; mf++) {
                uint32_t off = (uint32_t)((wm * 32 + mf * 16 + ar) * LDP + kof + ac) * 2;
                ldm_x4(ah[mf], sA_h + off);
                ldm_x4(al[mf], sA_l + off);
            }
#pragma unroll
            for (int g = 0; g < 4; g++) {
                uint32_t bh[4], bl[4];
                uint32_t off = (uint32_t)((wn * 64 + g * 16 + br) * LDP + kof + bc) * 2;
                ldm_x4(bh, sB_h + off);
                ldm_x4(bl, sB_l + off);
#pragma unroll
                for (int mf = 0; mf < 2; mf++) {
                    mma16816(acc[mf][2 * g],     ah[mf], bh);
                    mma16816(acc[mf][2 * g + 1], ah[mf], bh + 2);
                    mma16816(acc[mf][2 * g],     ah[mf], bl);
                    mma16816(acc[mf][2 * g + 1], ah[mf], bl + 2);
                    mma16816(acc[mf][2 * g],     al[mf], bh);
                    mma16816(acc[mf][2 * g + 1], al[mf], bh + 2);
                }
            }
        }
        __syncthreads();
    }

    // epilogue
    const int row_base = m0 + wm * 32 + (lane >> 2);
    const int col_loc  = (lane & 3) * 2;
#pragma unroll
    for (int mf = 0; mf < 2; mf++) {
#pragma unroll
        for (int nf = 0; nf < 8; nf++) {
            int c = n0 + wn * 64 + nf * 8 + col_loc;
            float2 bv = *(const float2*)&bias[c];
            int r0 = row_base + mf * 16;
            int r1 = r0 + 8;
            float v00 = acc[mf][nf][0] + bv.x;
            float v01 = acc[mf][nf][1] + bv.y;
            float v10 = acc[mf][nf][2] + bv.x;
            float v11 = acc[mf][nf][3] + bv.y;
            if (RELU) {
                v00 = fmaxf(v00, 0.f); v01 = fmaxf(v01, 0.f);
                v10 = fmaxf(v10, 0.f); v11 = fmaxf(v11, 0.f);
            }
            if (OUTMODE == 0) {
                *(float2*)&C[(size_t)r0 * N + c] = make_float2(v00, v01);
                *(float2*)&C[(size_t)r1 * N + c] = make_float2(v10, v11);
            } else {
                __nv_bfloat16 h0, l0, h1, l1;
                split_bf16(v00, h0, l0); split_bf16(v01, h1, l1);
                *(__nv_bfloat162*)&Chi[(size_t)r0 * N + c] = __nv_bfloat162(h0, h1);
                *(__nv_bfloat162*)&Clo[(size_t)r0 * N + c] = __nv_bfloat162(l0, l1);
                split_bf16(v10, h0, l0); split_bf16(v11, h1, l1);
                *(__nv_bfloat162*)&Chi[(size_t)r1 * N + c] = __nv_bfloat162(h0, h1);
                *(__nv_bfloat162*)&Clo[(size_t)r1 * N + c] = __nv_bfloat162(l0, l1);
            }
        }
    }
}

// ======================= persistent LSTM scan =======================
// outMode: 0 = no output, 1 = split-bf16 (yhi/ylo), 2 = fp32 (yfp)
__global__ __launch_bounds__(256, 2)
void lstm_scan(const float* __restrict__ xw, const float* __restrict__ bias,
               const float* __restrict__ Umat,
               __nv_bfloat16* __restrict__ yhi, __nv_bfloat16* __restrict__ ylo,
               float* __restrict__ yfp,
               int Tlen, int initFromState, int outMode)
{
    extern __shared__ float sm[];
    float* U_s = sm;
    float* h_s = sm + 16384;
    float* z_s = sm + 20480;

    const int tid = threadIdx.x;
    const int b0  = blockIdx.x * 16;
    const int u0  = blockIdx.y * 16;

    for (int idx = tid; idx < 16384; idx += 256) {
        int k = idx >> 6, c = idx & 63;
        U_s[idx] = Umat[k * G4 + (c >> 4) * UU + u0 + (c & 15)];
    }

    const int b_l = tid >> 4, u_l = tid & 15;
    const int gidx = (b0 + b_l) * UU + u0 + u_l;
    float c_reg = initFromState ? g_cfin[gidx] : 0.0f;
    g_hbuf[0][gidx] = initFromState ? g_hfin[gidx] : 0.0f;

    const int jj  = tid & 31;
    const int bq  = tid >> 5;
    const int j0  = jj << 1;
    const int bl0 = bq << 1;
    const int jglob0 = (j0 >> 4) * UU + u0 + (j0 & 15);

    grid_sync_256();

    for (int t = 0; t < Tlen; t++) {
        float a00, a01, a10, a11;
        if (xw) {
            float2 x0 = *(const float2*)(xw + ((size_t)(b0 + bl0) * Tlen + t) * G4 + jglob0);
            float2 x1 = *(const float2*)(xw + ((size_t)(b0 + bl0 + 1) * Tlen + t) * G4 + jglob0);
            a00 = x0.x; a01 = x0.y; a10 = x1.x; a11 = x1.y;
        } else {
            float2 bv = *(const float2*)&bias[jglob0];
            a00 = bv.x; a01 = bv.y; a10 = bv.x; a11 = bv.y;
        }

        {
            const float4* src = (const float4*)(g_hbuf[t & 1] + b0 * UU);
            float4* dst = (float4*)h_s;
#pragma unroll
            for (int r = 0; r < 4; r++)
                dst[tid + r * 256] = __ldcg(src + tid + r * 256);
        }
        __syncthreads();

        const float* hr0 = h_s + bl0 * 256;
        const float* hr1 = hr0 + 256;
        const float2* Uv = (const float2*)U_s;
#pragma unroll 4
        for (int k = 0; k < 256; k += 4) {
            float4 h0 = *(const float4*)(hr0 + k);
            float4 h1 = *(const float4*)(hr1 + k);
            float2 u0v = Uv[(k + 0) * 32 + jj];
            float2 u1v = Uv[(k + 1) * 32 + jj];
            float2 u2v = Uv[(k + 2) * 32 + jj];
            float2 u3v = Uv[(k + 3) * 32 + jj];
            a00 += h0.x * u0v.x; a01 += h0.x * u0v.y;
            a10 += h1.x * u0v.x; a11 += h1.x * u0v.y;
            a00 += h0.y * u1v.x; a01 += h0.y * u1v.y;
            a10 += h1.y * u1v.x; a11 += h1.y * u1v.y;
            a00 += h0.z * u2v.x; a01 += h0.z * u2v.y;
            a10 += h1.z * u2v.x; a11 += h1.z * u2v.y;
            a00 += h0.w * u3v.x; a01 += h0.w * u3v.y;
            a10 += h1.w * u3v.x; a11 += h1.w * u3v.y;
        }
        *(float2*)&z_s[ bl0      * 64 + j0] = make_float2(a00, a01);
        *(float2*)&z_s[(bl0 + 1) * 64 + j0] = make_float2(a10, a11);
        __syncthreads();

        {
            float zi = z_s[b_l * 64 +      u_l];
            float zf = z_s[b_l * 64 + 16 + u_l];
            float zg = z_s[b_l * 64 + 32 + u_l];
            float zo = z_s[b_l * 64 + 48 + u_l];
            float cn = sigm_f(zf) * c_reg + sigm_f(zi) * tanh_f(zg);
            float hn = sigm_f(zo) * tanh_f(cn);
            c_reg = cn;
            size_t oidx = ((size_t)(b0 + b_l) * Tlen + t) * UU + u0 + u_l;
            if (outMode == 1) {
                __nv_bfloat16 hh, ll; split_bf16(hn, hh, ll);
                yhi[oidx] = hh; ylo[oidx] = ll;
            } else if (outMode == 2) {
                yfp[oidx] = hn;
            }
            g_hbuf[(t + 1) & 1][gidx] = hn;
            if (t == Tlen - 1) { g_hfin[gidx] = hn; g_cfin[gidx] = cn; }
        }
        grid_sync_256();
    }
}

// ======================= decoder weight combine & dense =======================
__global__ void combine_w_kernel(const float* __restrict__ a, const float* __restrict__ b) {
    int i = blockIdx.x * 256 + threadIdx.x;
    g_wc[i] = a[i] + b[i];
}

__global__ void dense_kernel(const float* __restrict__ h, const float* __restrict__ w,
                             const float* __restrict__ b, float* __restrict__ out) {
    __shared__ float ws[UU * OD];
    for (int i = threadIdx.x; i < UU * OD; i += 256) ws[i] = w[i];
    __syncthreads();
    int idx = blockIdx.x * 256 + threadIdx.x;
    int o   = idx & 7;
    size_t row = idx >> 3;
    float acc = b[o];
    const float* hp = h + row * UU;
#pragma unroll 8
    for (int k = 0; k < UU; k++) acc += hp[k] * ws[k * OD + o];
    out[idx] = acc;
}

// ======================= launch =======================
extern "C" void kernel_launch(void* const* d_in, const int* in_sizes, int n_in,
                              void* d_out, int out_size)
{
    const float* x     = (const float*)d_in[0];
    const float* cnn_w = (const float*)d_in[1];
    const float* cnn_b = (const float*)d_in[2];
    const float* ew0 = (const float*)d_in[3];
    const float* eu0 = (const float*)d_in[4];
    const float* eb0 = (const float*)d_in[5];
    const float* ew1 = (const float*)d_in[6];
    const float* eu1 = (const float*)d_in[7];
    const float* eb1 = (const float*)d_in[8];
    const float* ew2 = (const float*)d_in[9];
    const float* eu2 = (const float*)d_in[10];
    const float* eb2 = (const float*)d_in[11];
    const float* cw  = (const float*)d_in[12];
    const float* cu  = (const float*)d_in[13];
    const float* cb  = (const float*)d_in[14];
    const float* dw  = (const float*)d_in[15];
    const float* db  = (const float*)d_in[16];
    float* out = (float*)d_out;

    __nv_bfloat16 *xch, *xcl, *ah, *al, *wth, *wtl, *cwth, *cwtl;
    float *xwp, *hdec, *wc;
    cudaGetSymbolAddress((void**)&xch,  g_xc_hi);
    cudaGetSymbolAddress((void**)&xcl,  g_xc_lo);
    cudaGetSymbolAddress((void**)&ah,   g_a_hi);
    cudaGetSymbolAddress((void**)&al,   g_a_lo);
    cudaGetSymbolAddress((void**)&wth,  g_wt_hi);
    cudaGetSymbolAddress((void**)&wtl,  g_wt_lo);
    cudaGetSymbolAddress((void**)&cwth, g_cwt_hi);
    cudaGetSymbolAddress((void**)&cwtl, g_cwt_lo);
    cudaGetSymbolAddress((void**)&xwp,  g_xw);
    cudaGetSymbolAddress((void**)&hdec, g_hdec);
    cudaGetSymbolAddress((void**)&wc,   g_wc);

    const int SCAN_SMEM = 21504 * 4;
    const int GEMM_SMEM = 4 * TILE_ELE * 2;   // 73728 B
    cudaFuncSetAttribute(lstm_scan, cudaFuncAttributeMaxDynamicSharedMemorySize, SCAN_SMEM);
    cudaFuncSetAttribute(mma_gemm<1,1>, cudaFuncAttributeMaxDynamicSharedMemorySize, GEMM_SMEM);
    cudaFuncSetAttribute(mma_gemm<0,0>, cudaFuncAttributeMaxDynamicSharedMemorySize, GEMM_SMEM);

    dim3 scan_grid(16, 16);

    // conv: im2col(split) + HMMA GEMM (bias+ReLU, split-bf16 out)
    im2col_split<<<(int)(((size_t)MTOT * KC) / 256), 256>>>(x);
    wsplit<<<(UU * KC + 255) / 256, 256>>>(cnn_w, cwth, cwtl, KC, UU);
    mma_gemm<1,1><<<dim3(UU / 128, MTOT / 128), 256, GEMM_SMEM>>>(
        xch, xcl, cwth, cwtl, cnn_b, nullptr, ah, al, MTOT, UU, KC);

    // encoder layer 0
    wsplit<<<(UU * G4) / 256, 256>>>(ew0, wth, wtl, UU, G4);
    mma_gemm<0,0><<<dim3(G4 / 128, MTOT / 128), 256, GEMM_SMEM>>>(
        ah, al, wth, wtl, eb0, xwp, nullptr, nullptr, MTOT, G4, UU);
    lstm_scan<<<scan_grid, 256, SCAN_SMEM>>>(xwp, nullptr, eu0, ah, al, nullptr, TT, 0, 1);

    // encoder layer 1
    wsplit<<<(UU * G4) / 256, 256>>>(ew1, wth, wtl, UU, G4);
    mma_gemm<0,0><<<dim3(G4 / 128, MTOT / 128), 256, GEMM_SMEM>>>(
        ah, al, wth, wtl, eb1, xwp, nullptr, nullptr, MTOT, G4, UU);
    lstm_scan<<<scan_grid, 256, SCAN_SMEM>>>(xwp, nullptr, eu1, ah, al, nullptr, TT, 0, 1);

    // encoder layer 2 (only final h,c needed)
    wsplit<<<(UU * G4) / 256, 256>>>(ew2, wth, wtl, UU, G4);
    mma_gemm<0,0><<<dim3(G4 / 128, MTOT / 128), 256, GEMM_SMEM>>>(
        ah, al, wth, wtl, eb2, xwp, nullptr, nullptr, MTOT, G4, UU);
    lstm_scan<<<scan_grid, 256, SCAN_SMEM>>>(xwp, nullptr, eu2, nullptr, nullptr, nullptr, TT, 0, 0);

    // decoder
    combine_w_kernel<<<(UU * G4) / 256, 256>>>(cw, cu);
    lstm_scan<<<scan_grid, 256, SCAN_SMEM>>>(nullptr, cb, wc, nullptr, nullptr, hdec, OUTS, 1, 2);

    // dense head
    dense_kernel<<<(BB * OUTS * OD) / 256, 256>>>(hdec, dw, db, out);
}

// round 6
// speedup vs baseline: 1.9097x; 1.6330x over previous
#include <cuda_runtime.h>
#include <cuda_bf16.h>
#include <cstdint>

#define BB    256
#define TT    512
#define FF    64
#define UU    256
#define G4    1024
#define KC    320
#define OUTS  64
#define OD    8
#define MTOT  (BB*TT)   // 131072

// ======================= device scratch =======================
__device__ __nv_bfloat16 g_xc_hi[(size_t)MTOT * KC];
__device__ __nv_bfloat16 g_xc_lo[(size_t)MTOT * KC];
__device__ __nv_bfloat16 g_a_hi [(size_t)MTOT * UU];
__device__ __nv_bfloat16 g_a_lo [(size_t)MTOT * UU];
__device__ __nv_bfloat16 g_wt_hi[G4 * UU];
__device__ __nv_bfloat16 g_wt_lo[G4 * UU];
__device__ __nv_bfloat16 g_ut_hi[G4 * UU];   // recurrent weights, transposed split
__device__ __nv_bfloat16 g_ut_lo[G4 * UU];
__device__ __nv_bfloat16 g_cwt_hi[UU * KC];
__device__ __nv_bfloat16 g_cwt_lo[UU * KC];
__device__ float g_xw  [(size_t)MTOT * G4];
__device__ float g_hbuf[2][BB * UU];
__device__ float g_hfin[BB * UU];
__device__ float g_cfin[BB * UU];
__device__ float g_hdec[(size_t)BB * OUTS * UU];
__device__ float g_wc  [UU * G4];
__device__ unsigned g_cnt_l[16 * 32];
__device__ unsigned g_cnt_g;
__device__ unsigned g_gen;

// ======================= PTX helpers (base-target only) =======================
__device__ __forceinline__ uint32_t smem_u32(const void* p) {
    uint32_t a;
    asm("{ .reg .u64 t; cvta.to.shared.u64 t, %1; cvt.u32.u64 %0, t; }" : "=r"(a) : "l"(p));
    return a;
}
__device__ __forceinline__ void ldm_x4(uint32_t* r, uint32_t addr) {
    asm volatile("ldmatrix.sync.aligned.m8n8.x4.shared.b16 {%0,%1,%2,%3}, [%4];"
        : "=r"(r[0]), "=r"(r[1]), "=r"(r[2]), "=r"(r[3]) : "r"(addr));
}
__device__ __forceinline__ void mma16816(float* d, const uint32_t* a, const uint32_t* b) {
    asm volatile("mma.sync.aligned.m16n8k16.row.col.f32.bf16.bf16.f32 "
        "{%0,%1,%2,%3}, {%4,%5,%6,%7}, {%8,%9}, {%0,%1,%2,%3};"
        : "+f"(d[0]), "+f"(d[1]), "+f"(d[2]), "+f"(d[3])
        : "r"(a[0]), "r"(a[1]), "r"(a[2]), "r"(a[3]), "r"(b[0]), "r"(b[1]));
}

// ======================= misc helpers =======================
__device__ __forceinline__ float sigm_f(float x) {
    return __fdividef(1.0f, 1.0f + __expf(-x));
}
__device__ __forceinline__ float tanh_f(float x) {
    float xc = fminf(fmaxf(x, -15.0f), 15.0f);
    float e  = __expf(-2.0f * xc);
    return __fdividef(1.0f - e, 1.0f + e);
}
__device__ __forceinline__ void split_bf16(float v, __nv_bfloat16& h, __nv_bfloat16& l) {
    h = __float2bfloat16(v);
    l = __float2bfloat16(v - __bfloat162float(h));
}

__device__ __forceinline__ void grid_sync_256() {
    __syncthreads();
    if (threadIdx.x == 0) {
        __threadfence();
        unsigned gen = *((volatile unsigned*)&g_gen);
        if (atomicAdd(&g_cnt_l[blockIdx.x * 32], 1u) == 15u) {
            if (atomicAdd(&g_cnt_g, 1u) == 15u) {
                for (int i = 0; i < 16; i++)
                    *((volatile unsigned*)&g_cnt_l[i * 32]) = 0u;
                *((volatile unsigned*)&g_cnt_g) = 0u;
                __threadfence();
                *((volatile unsigned*)&g_gen) = gen + 1u;
            }
        }
        while (*((volatile unsigned*)&g_gen) == gen) { __nanosleep(64); }
        __threadfence();
    }
    __syncthreads();
}

// ======================= im2col + split =======================
__global__ void im2col_split(const float* __restrict__ x) {
    size_t idx = (size_t)blockIdx.x * 256 + threadIdx.x;
    int col = (int)(idx % KC);
    size_t mt = idx / KC;
    int t = (int)(mt % TT);
    int b = (int)(mt / TT);
    int k = col >> 6, f = col & 63;
    int tt = t + k - 2;
    float v = (tt >= 0 && tt < TT) ? x[((size_t)b * TT + tt) * FF + f] : 0.0f;
    __nv_bfloat16 h, l; split_bf16(v, h, l);
    g_xc_hi[idx] = h; g_xc_lo[idx] = l;
}

// W[K,N] -> Wt_hi/lo[N,K] bf16 (transpose + split)
__global__ void wsplit(const float* __restrict__ W, __nv_bfloat16* __restrict__ hi,
                       __nv_bfloat16* __restrict__ lo, int K, int N) {
    int idx = blockIdx.x * 256 + threadIdx.x;
    if (idx >= K * N) return;
    int n = idx / K, k = idx % K;
    float v = W[(size_t)k * N + n];
    __nv_bfloat16 h, l; split_bf16(v, h, l);
    hi[idx] = h; lo[idx] = l;
}

// ======================= HMMA split-bf16 GEMM =======================
#define LDP 72
#define TILE_ELE (128 * LDP)

template<int RELU, int OUTMODE>
__global__ __launch_bounds__(256)
void mma_gemm(const __nv_bfloat16* __restrict__ Ahi, const __nv_bfloat16* __restrict__ Alo,
              const __nv_bfloat16* __restrict__ Bhi, const __nv_bfloat16* __restrict__ Blo,
              const float* __restrict__ bias,
              float* __restrict__ C,
              __nv_bfloat16* __restrict__ Chi, __nv_bfloat16* __restrict__ Clo,
              int M, int N, int K)
{
    extern __shared__ __nv_bfloat16 smem[];
    __nv_bfloat16* As_h = smem;
    __nv_bfloat16* As_l = smem + TILE_ELE;
    __nv_bfloat16* Bs_h = smem + 2 * TILE_ELE;
    __nv_bfloat16* Bs_l = smem + 3 * TILE_ELE;

    const int tid  = threadIdx.x;
    const int lane = tid & 31;
    const int wid  = tid >> 5;
    const int wm   = wid & 3;
    const int wn   = wid >> 2;
    const int n0 = blockIdx.x * 128;
    const int m0 = blockIdx.y * 128;

    float acc[2][8][4];
#pragma unroll
    for (int i = 0; i < 2; i++)
#pragma unroll
        for (int j = 0; j < 8; j++)
#pragma unroll
            for (int q = 0; q < 4; q++) acc[i][j][q] = 0.0f;

    const int ar = lane & 15, ac = (lane >> 4) << 3;
    const int br = (lane & 7) + ((lane >> 4) << 3);
    const int bc = ((lane >> 3) & 1) << 3;
    const uint32_t sA_h = smem_u32(As_h), sA_l = smem_u32(As_l);
    const uint32_t sB_h = smem_u32(Bs_h), sB_l = smem_u32(Bs_l);

    for (int k0 = 0; k0 < K; k0 += 64) {
#pragma unroll
        for (int r = 0; r < 4; r++) {
            int unit = tid + r * 256;
            int row = unit >> 3, c8 = (unit & 7) << 3;
            size_t ga = (size_t)(m0 + row) * K + k0 + c8;
            size_t gb = (size_t)(n0 + row) * K + k0 + c8;
            *(uint4*)&As_h[row * LDP + c8] = *(const uint4*)&Ahi[ga];
            *(uint4*)&As_l[row * LDP + c8] = *(const uint4*)&Alo[ga];
            *(uint4*)&Bs_h[row * LDP + c8] = *(const uint4*)&Bhi[gb];
            *(uint4*)&Bs_l[row * LDP + c8] = *(const uint4*)&Blo[gb];
        }
        __syncthreads();

#pragma unroll
        for (int kk = 0; kk < 4; kk++) {
            const int kof = kk * 16;
            uint32_t ah[2][4], al[2][4];
#pragma unroll
            for (int mf = 0; mf < 2; mf++) {
                uint32_t off = (uint32_t)((wm * 32 + mf * 16 + ar) * LDP + kof + ac) * 2;
                ldm_x4(ah[mf], sA_h + off);
                ldm_x4(al[mf], sA_l + off);
            }
#pragma unroll
            for (int g = 0; g < 4; g++) {
                uint32_t bh[4], bl[4];
                uint32_t off = (uint32_t)((wn * 64 + g * 16 + br) * LDP + kof + bc) * 2;
                ldm_x4(bh, sB_h + off);
                ldm_x4(bl, sB_l + off);
#pragma unroll
                for (int mf = 0; mf < 2; mf++) {
                    mma16816(acc[mf][2 * g],     ah[mf], bh);
                    mma16816(acc[mf][2 * g + 1], ah[mf], bh + 2);
                    mma16816(acc[mf][2 * g],     ah[mf], bl);
                    mma16816(acc[mf][2 * g + 1], ah[mf], bl + 2);
                    mma16816(acc[mf][2 * g],     al[mf], bh);
                    mma16816(acc[mf][2 * g + 1], al[mf], bh + 2);
                }
            }
        }
        __syncthreads();
    }

    const int row_base = m0 + wm * 32 + (lane >> 2);
    const int col_loc  = (lane & 3) * 2;
#pragma unroll
    for (int mf = 0; mf < 2; mf++) {
#pragma unroll
        for (int nf = 0; nf < 8; nf++) {
            int c = n0 + wn * 64 + nf * 8 + col_loc;
            float2 bv = *(const float2*)&bias[c];
            int r0 = row_base + mf * 16;
            int r1 = r0 + 8;
            float v00 = acc[mf][nf][0] + bv.x;
            float v01 = acc[mf][nf][1] + bv.y;
            float v10 = acc[mf][nf][2] + bv.x;
            float v11 = acc[mf][nf][3] + bv.y;
            if (RELU) {
                v00 = fmaxf(v00, 0.f); v01 = fmaxf(v01, 0.f);
                v10 = fmaxf(v10, 0.f); v11 = fmaxf(v11, 0.f);
            }
            if (OUTMODE == 0) {
                *(float2*)&C[(size_t)r0 * N + c] = make_float2(v00, v01);
                *(float2*)&C[(size_t)r1 * N + c] = make_float2(v10, v11);
            } else {
                __nv_bfloat16 h0, l0, h1, l1;
                split_bf16(v00, h0, l0); split_bf16(v01, h1, l1);
                *(__nv_bfloat162*)&Chi[(size_t)r0 * N + c] = __nv_bfloat162(h0, h1);
                *(__nv_bfloat162*)&Clo[(size_t)r0 * N + c] = __nv_bfloat162(l0, l1);
                split_bf16(v10, h0, l0); split_bf16(v11, h1, l1);
                *(__nv_bfloat162*)&Chi[(size_t)r1 * N + c] = __nv_bfloat162(h0, h1);
                *(__nv_bfloat162*)&Clo[(size_t)r1 * N + c] = __nv_bfloat162(l0, l1);
            }
        }
    }
}

// ======================= persistent HMMA LSTM scan =======================
// grid (16,16): 16 batch rows x 16 units (64 gate cols) per block, 8 warps.
// Warp w owns 8 gate cols: gate = w>>1, units (w&1)*8 + lane/4. Its split-bf16
// U fragments (16 k-chunks x 2 regs x hi/lo = 64 regs) stay in registers for
// the entire scan. Per step: stage h (fp32 -> split bf16 smem), ldmatrix A
// frags, 48 HMMA/warp, z -> smem, gate math (one (b,u) per thread).
#define HSS 264   // padded bf16 row stride for h staging (conflict-free ldmatrix)

__global__ __launch_bounds__(256, 2)
void lstm_scan_mma(const float* __restrict__ xw, const float* __restrict__ bias,
                   const __nv_bfloat16* __restrict__ Uth,
                   const __nv_bfloat16* __restrict__ Utl,
                   __nv_bfloat16* __restrict__ yhi, __nv_bfloat16* __restrict__ ylo,
                   float* __restrict__ yfp,
                   int Tlen, int initFromState, int outMode)
{
    __shared__ __nv_bfloat16 hs_h[16 * HSS];
    __shared__ __nv_bfloat16 hs_l[16 * HSS];
    __shared__ float z_s[16 * 66];

    const int tid = threadIdx.x, lane = tid & 31, wid = tid >> 5;
    const int b0 = blockIdx.x * 16, u0 = blockIdx.y * 16;

    // ---- register-resident B fragments (PTX m16n8k16 row.col B layout) ----
    // n = lane>>2, k pair base = (lane&3)*2 within each 16-chunk (+8 for reg1)
    const int gate = wid >> 1;
    const int jB = gate * UU + u0 + ((wid & 1) << 3) + (lane >> 2);
    const __nv_bfloat16* uhp = Uth + (size_t)jB * UU;
    const __nv_bfloat16* ulp = Utl + (size_t)jB * UU;
    uint32_t bh[16][2], bl[16][2];
    const int kq = (lane & 3) << 1;
#pragma unroll
    for (int kc = 0; kc < 16; kc++) {
        bh[kc][0] = *(const uint32_t*)&uhp[kc * 16 + kq];
        bh[kc][1] = *(const uint32_t*)&uhp[kc * 16 + kq + 8];
        bl[kc][0] = *(const uint32_t*)&ulp[kc * 16 + kq];
        bl[kc][1] = *(const uint32_t*)&ulp[kc * 16 + kq + 8];
    }

    // ---- per-thread state (one (b,u) cell) ----
    const int b_l = tid >> 4, u_l = tid & 15;
    const int gidx = (b0 + b_l) * UU + u0 + u_l;
    float c_reg = initFromState ? g_cfin[gidx] : 0.0f;
    g_hbuf[0][gidx] = initFromState ? g_hfin[gidx] : 0.0f;

    // decoder-mode bias (hoisted; encoder xw already includes bias)
    float bi = 0.f, bf = 0.f, bg = 0.f, bo = 0.f;
    if (!xw) {
        bi = bias[u0 + u_l];        bf = bias[256 + u0 + u_l];
        bg = bias[512 + u0 + u_l];  bo = bias[768 + u0 + u_l];
    }

    const uint32_t sh_h = smem_u32(hs_h);
    const uint32_t sh_l = smem_u32(hs_l);
    const uint32_t aoff = (uint32_t)((lane & 15) * HSS + ((lane >> 4) << 3)) * 2;

    grid_sync_256();

    for (int t = 0; t < Tlen; t++) {
        // ---- stage h: fp32 -> split bf16 hi/lo in smem ----
        {
            const float4* src = (const float4*)(g_hbuf[t & 1] + b0 * UU);
#pragma unroll
            for (int it = 0; it < 4; it++) {
                int i = tid + it * 256;           // 1024 float4 units
                float4 v = __ldcg(src + i);
                int row = i >> 6, c4 = (i & 63) << 2;
                __nv_bfloat16 h0, l0, h1, l1, h2, l2, h3, l3;
                split_bf16(v.x, h0, l0); split_bf16(v.y, h1, l1);
                split_bf16(v.z, h2, l2); split_bf16(v.w, h3, l3);
                __nv_bfloat162* ph = (__nv_bfloat162*)&hs_h[row * HSS + c4];
                __nv_bfloat162* pl = (__nv_bfloat162*)&hs_l[row * HSS + c4];
                ph[0] = __nv_bfloat162(h0, h1); ph[1] = __nv_bfloat162(h2, h3);
                pl[0] = __nv_bfloat162(l0, l1); pl[1] = __nv_bfloat162(l2, l3);
            }
        }
        __syncthreads();

        // ---- z = h @ U on tensor cores (3-pass split) ----
        float acc[4] = {0.f, 0.f, 0.f, 0.f};
#pragma unroll
        for (int kc = 0; kc < 16; kc++) {
            uint32_t ah[4], al4[4];
            uint32_t off = aoff + (uint32_t)(kc * 16) * 2;
            ldm_x4(ah,  sh_h + off);
            ldm_x4(al4, sh_l + off);
            mma16816(acc, ah,  bh[kc]);
            mma16816(acc, ah,  bl[kc]);
            mma16816(acc, al4, bh[kc]);
        }
        {
            int r = lane >> 2, cl = wid * 8 + ((lane & 3) << 1);
            *(float2*)&z_s[r * 66 + cl]       = make_float2(acc[0], acc[1]);
            *(float2*)&z_s[(r + 8) * 66 + cl] = make_float2(acc[2], acc[3]);
        }
        __syncthreads();

        // ---- gates: one (b,u) per thread ----
        {
            float zi = z_s[b_l * 66 +      u_l];
            float zf = z_s[b_l * 66 + 16 + u_l];
            float zg = z_s[b_l * 66 + 32 + u_l];
            float zo = z_s[b_l * 66 + 48 + u_l];
            if (xw) {
                const float* xr = xw + ((size_t)(b0 + b_l) * Tlen + t) * G4;
                zi += xr[      u0 + u_l];
                zf += xr[256 + u0 + u_l];
                zg += xr[512 + u0 + u_l];
                zo += xr[768 + u0 + u_l];
            } else {
                zi += bi; zf += bf; zg += bg; zo += bo;
            }
            float cn = sigm_f(zf) * c_reg + sigm_f(zi) * tanh_f(zg);
            float hn = sigm_f(zo) * tanh_f(cn);
            c_reg = cn;
            size_t oidx = ((size_t)(b0 + b_l) * Tlen + t) * UU + u0 + u_l;
            if (outMode == 1) {
                __nv_bfloat16 hh, ll; split_bf16(hn, hh, ll);
                yhi[oidx] = hh; ylo[oidx] = ll;
            } else if (outMode == 2) {
                yfp[oidx] = hn;
            }
            g_hbuf[(t + 1) & 1][gidx] = hn;
            if (t == Tlen - 1) { g_hfin[gidx] = hn; g_cfin[gidx] = cn; }
        }
        grid_sync_256();
    }
}

// ======================= decoder weight combine & dense =======================
__global__ void combine_w_kernel(const float* __restrict__ a, const float* __restrict__ b) {
    int i = blockIdx.x * 256 + threadIdx.x;
    g_wc[i] = a[i] + b[i];
}

__global__ void dense_kernel(const float* __restrict__ h, const float* __restrict__ w,
                             const float* __restrict__ b, float* __restrict__ out) {
    __shared__ float ws[UU * OD];
    for (int i = threadIdx.x; i < UU * OD; i += 256) ws[i] = w[i];
    __syncthreads();
    int idx = blockIdx.x * 256 + threadIdx.x;
    int o   = idx & 7;
    size_t row = idx >> 3;
    float acc = b[o];
    const float* hp = h + row * UU;
#pragma unroll 8
    for (int k = 0; k < UU; k++) acc += hp[k] * ws[k * OD + o];
    out[idx] = acc;
}

// ======================= launch =======================
extern "C" void kernel_launch(void* const* d_in, const int* in_sizes, int n_in,
                              void* d_out, int out_size)
{
    const float* x     = (const float*)d_in[0];
    const float* cnn_w = (const float*)d_in[1];
    const float* cnn_b = (const float*)d_in[2];
    const float* ew0 = (const float*)d_in[3];
    const float* eu0 = (const float*)d_in[4];
    const float* eb0 = (const float*)d_in[5];
    const float* ew1 = (const float*)d_in[6];
    const float* eu1 = (const float*)d_in[7];
    const float* eb1 = (const float*)d_in[8];
    const float* ew2 = (const float*)d_in[9];
    const float* eu2 = (const float*)d_in[10];
    const float* eb2 = (const float*)d_in[11];
    const float* cw  = (const float*)d_in[12];
    const float* cu  = (const float*)d_in[13];
    const float* cb  = (const float*)d_in[14];
    const float* dw  = (const float*)d_in[15];
    const float* db  = (const float*)d_in[16];
    float* out = (float*)d_out;

    __nv_bfloat16 *xch, *xcl, *ah, *al, *wth, *wtl, *uth, *utl, *cwth, *cwtl;
    float *xwp, *hdec, *wc;
    cudaGetSymbolAddress((void**)&xch,  g_xc_hi);
    cudaGetSymbolAddress((void**)&xcl,  g_xc_lo);
    cudaGetSymbolAddress((void**)&ah,   g_a_hi);
    cudaGetSymbolAddress((void**)&al,   g_a_lo);
    cudaGetSymbolAddress((void**)&wth,  g_wt_hi);
    cudaGetSymbolAddress((void**)&wtl,  g_wt_lo);
    cudaGetSymbolAddress((void**)&uth,  g_ut_hi);
    cudaGetSymbolAddress((void**)&utl,  g_ut_lo);
    cudaGetSymbolAddress((void**)&cwth, g_cwt_hi);
    cudaGetSymbolAddress((void**)&cwtl, g_cwt_lo);
    cudaGetSymbolAddress((void**)&xwp,  g_xw);
    cudaGetSymbolAddress((void**)&hdec, g_hdec);
    cudaGetSymbolAddress((void**)&wc,   g_wc);

    const int GEMM_SMEM = 4 * TILE_ELE * 2;
    cudaFuncSetAttribute(mma_gemm<1,1>, cudaFuncAttributeMaxDynamicSharedMemorySize, GEMM_SMEM);
    cudaFuncSetAttribute(mma_gemm<0,0>, cudaFuncAttributeMaxDynamicSharedMemorySize, GEMM_SMEM);

    dim3 scan_grid(16, 16);

    // conv: im2col(split) + HMMA GEMM (bias+ReLU, split-bf16 out)
    im2col_split<<<(int)(((size_t)MTOT * KC) / 256), 256>>>(x);
    wsplit<<<(UU * KC + 255) / 256, 256>>>(cnn_w, cwth, cwtl, KC, UU);
    mma_gemm<1,1><<<dim3(UU / 128, MTOT / 128), 256, GEMM_SMEM>>>(
        xch, xcl, cwth, cwtl, cnn_b, nullptr, ah, al, MTOT, UU, KC);

    // encoder layer 0
    wsplit<<<(UU * G4) / 256, 256>>>(ew0, wth, wtl, UU, G4);
    mma_gemm<0,0><<<dim3(G4 / 128, MTOT / 128), 256, GEMM_SMEM>>>(
        ah, al, wth, wtl, eb0, xwp, nullptr, nullptr, MTOT, G4, UU);
    wsplit<<<(UU * G4) / 256, 256>>>(eu0, uth, utl, UU, G4);
    lstm_scan_mma<<<scan_grid, 256>>>(xwp, nullptr, uth, utl, ah, al, nullptr, TT, 0, 1);

    // encoder layer 1
    wsplit<<<(UU * G4) / 256, 256>>>(ew1, wth, wtl, UU, G4);
    mma_gemm<0,0><<<dim3(G4 / 128, MTOT / 128), 256, GEMM_SMEM>>>(
        ah, al, wth, wtl, eb1, xwp, nullptr, nullptr, MTOT, G4, UU);
    wsplit<<<(UU * G4) / 256, 256>>>(eu1, uth, utl, UU, G4);
    lstm_scan_mma<<<scan_grid, 256>>>(xwp, nullptr, uth, utl, ah, al, nullptr, TT, 0, 1);

    // encoder layer 2 (only final h,c needed)
    wsplit<<<(UU * G4) / 256, 256>>>(ew2, wth, wtl, UU, G4);
    mma_gemm<0,0><<<dim3(G4 / 128, MTOT / 128), 256, GEMM_SMEM>>>(
        ah, al, wth, wtl, eb2, xwp, nullptr, nullptr, MTOT, G4, UU);
    wsplit<<<(UU * G4) / 256, 256>>>(eu2, uth, utl, UU, G4);
    lstm_scan_mma<<<scan_grid, 256>>>(xwp, nullptr, uth, utl, nullptr, nullptr, nullptr, TT, 0, 0);

    // decoder: z = h @ (cell_w + cell_u) + b, 64 steps from (h,c)
    combine_w_kernel<<<(UU * G4) / 256, 256>>>(cw, cu);
    wsplit<<<(UU * G4) / 256, 256>>>(wc, uth, utl, UU, G4);
    lstm_scan_mma<<<scan_grid, 256>>>(nullptr, cb, uth, utl, nullptr, nullptr, hdec, OUTS, 1, 2);

    // dense head
    dense_kernel<<<(BB * OUTS * OD) / 256, 256>>>(hdec, dw, db, out);
}

// round 9
// speedup vs baseline: 2.4688x; 1.2928x over previous
#include <cuda_runtime.h>
#include <cuda_bf16.h>
#include <cstdint>

#define BB    256
#define TT    512
#define FF    64
#define UU    256
#define G4    1024
#define KC    320
#define OUTS  64
#define OD    8
#define MTOT  (BB*TT)   // 131072

// ======================= device scratch =======================
__device__ __nv_bfloat16 g_xc_hi[(size_t)MTOT * KC];
__device__ __nv_bfloat16 g_xc_lo[(size_t)MTOT * KC];
__device__ __nv_bfloat16 g_a_hi [(size_t)MTOT * UU];
__device__ __nv_bfloat16 g_a_lo [(size_t)MTOT * UU];
__device__ __nv_bfloat16 g_wt_hi[G4 * UU];
__device__ __nv_bfloat16 g_wt_lo[G4 * UU];
__device__ __nv_bfloat16 g_ut_hi[G4 * UU];
__device__ __nv_bfloat16 g_ut_lo[G4 * UU];
__device__ __nv_bfloat16 g_cwt_hi[UU * KC];
__device__ __nv_bfloat16 g_cwt_lo[UU * KC];
__device__ float g_xw  [(size_t)MTOT * G4];
__device__ __nv_bfloat16 g_hb_hi[2][BB * UU];   // split h ping-pong
__device__ __nv_bfloat16 g_hb_lo[2][BB * UU];
__device__ float g_hfin[BB * UU];
__device__ float g_cfin[BB * UU];
__device__ float g_hdec[(size_t)BB * OUTS * UU];
__device__ float g_wc  [UU * G4];
__device__ unsigned g_bar[16 * 32];   // per-b-group monotone barrier counters

// ======================= PTX helpers (base-target only) =======================
__device__ __forceinline__ uint32_t smem_u32(const void* p) {
    uint32_t a;
    asm("{ .reg .u64 t; cvta.to.shared.u64 t, %1; cvt.u32.u64 %0, t; }" : "=r"(a) : "l"(p));
    return a;
}
__device__ __forceinline__ void ldm_x4(uint32_t* r, uint32_t addr) {
    asm volatile("ldmatrix.sync.aligned.m8n8.x4.shared.b16 {%0,%1,%2,%3}, [%4];"
        : "=r"(r[0]), "=r"(r[1]), "=r"(r[2]), "=r"(r[3]) : "r"(addr));
}
__device__ __forceinline__ void mma16816(float* d, const uint32_t* a, const uint32_t* b) {
    asm volatile("mma.sync.aligned.m16n8k16.row.col.f32.bf16.bf16.f32 "
        "{%0,%1,%2,%3}, {%4,%5,%6,%7}, {%8,%9}, {%0,%1,%2,%3};"
        : "+f"(d[0]), "+f"(d[1]), "+f"(d[2]), "+f"(d[3])
        : "r"(a[0]), "r"(a[1]), "r"(a[2]), "r"(a[3]), "r"(b[0]), "r"(b[1]));
}

// ======================= misc helpers =======================
__device__ __forceinline__ float sigm_f(float x) {
    return __fdividef(1.0f, 1.0f + __expf(-x));
}
__device__ __forceinline__ float tanh_f(float x) {
    float xc = fminf(fmaxf(x, -15.0f), 15.0f);
    float e  = __expf(-2.0f * xc);
    return __fdividef(1.0f - e, 1.0f + e);
}
__device__ __forceinline__ void split_bf16(float v, __nv_bfloat16& h, __nv_bfloat16& l) {
    h = __float2bfloat16(v);
    l = __float2bfloat16(v - __bfloat162float(h));
}

// Monotone per-group barrier. Counter only increases within a launch; a
// bar_reset launch zeroes it before every scan. No reset inside the kernel,
// no generation word => no reset/ABA race, deterministic across replays.
__device__ __forceinline__ void group_sync(int grp, unsigned target) {
    __syncthreads();
    if (threadIdx.x == 0) {
        __threadfence();
        atomicAdd(&g_bar[grp * 32], 1u);
        volatile unsigned* p = &g_bar[grp * 32];
        while (*p < target) { __nanosleep(32); }
        __threadfence();
    }
    __syncthreads();
}

__global__ void bar_reset() {
    if (threadIdx.x < 16) g_bar[threadIdx.x * 32] = 0u;
}

// ======================= im2col + split =======================
__global__ void im2col_split(const float* __restrict__ x) {
    size_t idx = (size_t)blockIdx.x * 256 + threadIdx.x;
    int col = (int)(idx % KC);
    size_t mt = idx / KC;
    int t = (int)(mt % TT);
    int b = (int)(mt / TT);
    int k = col >> 6, f = col & 63;
    int tt = t + k - 2;
    float v = (tt >= 0 && tt < TT) ? x[((size_t)b * TT + tt) * FF + f] : 0.0f;
    __nv_bfloat16 h, l; split_bf16(v, h, l);
    g_xc_hi[idx] = h; g_xc_lo[idx] = l;
}

// W[K,N] -> Wt_hi/lo[N,K] bf16 (transpose + split)
__global__ void wsplit(const float* __restrict__ W, __nv_bfloat16* __restrict__ hi,
                       __nv_bfloat16* __restrict__ lo, int K, int N) {
    int idx = blockIdx.x * 256 + threadIdx.x;
    if (idx >= K * N) return;
    int n = idx / K, k = idx % K;
    float v = W[(size_t)k * N + n];
    __nv_bfloat16 h, l; split_bf16(v, h, l);
    hi[idx] = h; lo[idx] = l;
}

// ======================= HMMA split-bf16 GEMM =======================
#define LDP 72
#define TILE_ELE (128 * LDP)

template<int RELU, int OUTMODE>
__global__ __launch_bounds__(256)
void mma_gemm(const __nv_bfloat16* __restrict__ Ahi, const __nv_bfloat16* __restrict__ Alo,
              const __nv_bfloat16* __restrict__ Bhi, const __nv_bfloat16* __restrict__ Blo,
              const float* __restrict__ bias,
              float* __restrict__ C,
              __nv_bfloat16* __restrict__ Chi, __nv_bfloat16* __restrict__ Clo,
              int M, int N, int K)
{
    extern __shared__ __nv_bfloat16 smem[];
    __nv_bfloat16* As_h = smem;
    __nv_bfloat16* As_l = smem + TILE_ELE;
    __nv_bfloat16* Bs_h = smem + 2 * TILE_ELE;
    __nv_bfloat16* Bs_l = smem + 3 * TILE_ELE;

    const int tid  = threadIdx.x;
    const int lane = tid & 31;
    const int wid  = tid >> 5;
    const int wm   = wid & 3;
    const int wn   = wid >> 2;
    const int n0 = blockIdx.x * 128;
    const int m0 = blockIdx.y * 128;

    float acc[2][8][4];
#pragma unroll
    for (int i = 0; i < 2; i++)
#pragma unroll
        for (int j = 0; j < 8; j++)
#pragma unroll
            for (int q = 0; q < 4; q++) acc[i][j][q] = 0.0f;

    const int ar = lane & 15, ac = (lane >> 4) << 3;
    const int br = (lane & 7) + ((lane >> 4) << 3);
    const int bc = ((lane >> 3) & 1) << 3;
    const uint32_t sA_h = smem_u32(As_h), sA_l = smem_u32(As_l);
    const uint32_t sB_h = smem_u32(Bs_h), sB_l = smem_u32(Bs_l);

    for (int k0 = 0; k0 < K; k0 += 64) {
#pragma unroll
        for (int r = 0; r < 4; r++) {
            int unit = tid + r * 256;
            int row = unit >> 3, c8 = (unit & 7) << 3;
            size_t ga = (size_t)(m0 + row) * K + k0 + c8;
            size_t gb = (size_t)(n0 + row) * K + k0 + c8;
            *(uint4*)&As_h[row * LDP + c8] = *(const uint4*)&Ahi[ga];
            *(uint4*)&As_l[row * LDP + c8] = *(const uint4*)&Alo[ga];
            *(uint4*)&Bs_h[row * LDP + c8] = *(const uint4*)&Bhi[gb];
            *(uint4*)&Bs_l[row * LDP + c8] = *(const uint4*)&Blo[gb];
        }
        __syncthreads();

#pragma unroll
        for (int kk = 0; kk < 4; kk++) {
            const int kof = kk * 16;
            uint32_t ah[2][4], al[2][4];
#pragma unroll
            for (int mf = 0; mf < 2; mf++) {
                uint32_t off = (uint32_t)((wm * 32 + mf * 16 + ar) * LDP + kof + ac) * 2;
                ldm_x4(ah[mf], sA_h + off);
                ldm_x4(al[mf], sA_l + off);
            }
#pragma unroll
            for (int g = 0; g < 4; g++) {
                uint32_t bh[4], bl[4];
                uint32_t off = (uint32_t)((wn * 64 + g * 16 + br) * LDP + kof + bc) * 2;
                ldm_x4(bh, sB_h + off);
                ldm_x4(bl, sB_l + off);
#pragma unroll
                for (int mf = 0; mf < 2; mf++) {
                    mma16816(acc[mf][2 * g],     ah[mf], bh);
                    mma16816(acc[mf][2 * g + 1], ah[mf], bh + 2);
                    mma16816(acc[mf][2 * g],     ah[mf], bl);
                    mma16816(acc[mf][2 * g + 1], ah[mf], bl + 2);
                    mma16816(acc[mf][2 * g],     al[mf], bh);
                    mma16816(acc[mf][2 * g + 1], al[mf], bh + 2);
                }
            }
        }
        __syncthreads();
    }

    const int row_base = m0 + wm * 32 + (lane >> 2);
    const int col_loc  = (lane & 3) * 2;
#pragma unroll
    for (int mf = 0; mf < 2; mf++) {
#pragma unroll
        for (int nf = 0; nf < 8; nf++) {
            int c = n0 + wn * 64 + nf * 8 + col_loc;
            float2 bv = *(const float2*)&bias[c];
            int r0 = row_base + mf * 16;
            int r1 = r0 + 8;
            float v00 = acc[mf][nf][0] + bv.x;
            float v01 = acc[mf][nf][1] + bv.y;
            float v10 = acc[mf][nf][2] + bv.x;
            float v11 = acc[mf][nf][3] + bv.y;
            if (RELU) {
                v00 = fmaxf(v00, 0.f); v01 = fmaxf(v01, 0.f);
                v10 = fmaxf(v10, 0.f); v11 = fmaxf(v11, 0.f);
            }
            if (OUTMODE == 0) {
                *(float2*)&C[(size_t)r0 * N + c] = make_float2(v00, v01);
                *(float2*)&C[(size_t)r1 * N + c] = make_float2(v10, v11);
            } else {
                __nv_bfloat16 h0, l0, h1, l1;
                split_bf16(v00, h0, l0); split_bf16(v01, h1, l1);
                *(__nv_bfloat162*)&Chi[(size_t)r0 * N + c] = __nv_bfloat162(h0, h1);
                *(__nv_bfloat162*)&Clo[(size_t)r0 * N + c] = __nv_bfloat162(l0, l1);
                split_bf16(v10, h0, l0); split_bf16(v11, h1, l1);
                *(__nv_bfloat162*)&Chi[(size_t)r1 * N + c] = __nv_bfloat162(h0, h1);
                *(__nv_bfloat162*)&Clo[(size_t)r1 * N + c] = __nv_bfloat162(l0, l1);
            }
        }
    }
}

// ======================= persistent HMMA LSTM scan =======================
// grid (16,16): blockIdx.x = b-group (16 batch rows), blockIdx.y = u-tile.
// Only the 16 blocks of a b-group synchronize (batch rows independent).
// U fragments register-resident; h exchanged as split bf16 ping-pong.
#define HSS 264

__global__ __launch_bounds__(256, 2)
void lstm_scan_mma(const float* __restrict__ xw, const float* __restrict__ bias,
                   const __nv_bfloat16* __restrict__ Uth,
                   const __nv_bfloat16* __restrict__ Utl,
                   __nv_bfloat16* __restrict__ yhi, __nv_bfloat16* __restrict__ ylo,
                   float* __restrict__ yfp,
                   int Tlen, int initFromState, int outMode)
{
    __shared__ __nv_bfloat16 hs_h[16 * HSS];
    __shared__ __nv_bfloat16 hs_l[16 * HSS];
    __shared__ float z_s[16 * 66];

    const int tid = threadIdx.x, lane = tid & 31, wid = tid >> 5;
    const int grp = blockIdx.x;
    const int b0 = blockIdx.x * 16, u0 = blockIdx.y * 16;

    // ---- register-resident B fragments (m16n8k16 row.col B layout) ----
    const int gate = wid >> 1;
    const int jB = gate * UU + u0 + ((wid & 1) << 3) + (lane >> 2);
    const __nv_bfloat16* uhp = Uth + (size_t)jB * UU;
    const __nv_bfloat16* ulp = Utl + (size_t)jB * UU;
    uint32_t bh[16][2], bl[16][2];
    const int kq = (lane & 3) << 1;
#pragma unroll
    for (int kc = 0; kc < 16; kc++) {
        bh[kc][0] = *(const uint32_t*)&uhp[kc * 16 + kq];
        bh[kc][1] = *(const uint32_t*)&uhp[kc * 16 + kq + 8];
        bl[kc][0] = *(const uint32_t*)&ulp[kc * 16 + kq];
        bl[kc][1] = *(const uint32_t*)&ulp[kc * 16 + kq + 8];
    }

    // ---- per-thread state (one (b,u) cell) ----
    const int b_l = tid >> 4, u_l = tid & 15;
    const int gidx = (b0 + b_l) * UU + u0 + u_l;
    float c_reg = initFromState ? g_cfin[gidx] : 0.0f;
    {
        float h0v = initFromState ? g_hfin[gidx] : 0.0f;
        __nv_bfloat16 hh, ll; split_bf16(h0v, hh, ll);
        g_hb_hi[0][gidx] = hh; g_hb_lo[0][gidx] = ll;
    }

    // decoder-mode bias (encoder xw already includes bias)
    float bi = 0.f, bf = 0.f, bg = 0.f, bo = 0.f;
    if (!xw) {
        bi = bias[u0 + u_l];        bf = bias[256 + u0 + u_l];
        bg = bias[512 + u0 + u_l];  bo = bias[768 + u0 + u_l];
    }

    const uint32_t sh_h = smem_u32(hs_h);
    const uint32_t sh_l = smem_u32(hs_l);
    const uint32_t aoff = (uint32_t)((lane & 15) * HSS + ((lane >> 4) << 3)) * 2;

    group_sync(grp, 16u);                       // barrier #0

    for (int t = 0; t < Tlen; t++) {
        // ---- prefetch per-step additive term (overlaps staging + MMA) ----
        float xi, xf2, xg, xo;
        if (xw) {
            const float* xr = xw + ((size_t)(b0 + b_l) * Tlen + t) * G4;
            xi  = __ldcg(xr +        u0 + u_l);
            xf2 = __ldcg(xr + 256 +  u0 + u_l);
            xg  = __ldcg(xr + 512 +  u0 + u_l);
            xo  = __ldcg(xr + 768 +  u0 + u_l);
        } else {
            xi = bi; xf2 = bf; xg = bg; xo = bo;
        }

        // ---- stage split h: plain bf16 copy, no conversions ----
        {
            const uint4* sh = (const uint4*)(g_hb_hi[t & 1] + b0 * UU);
            const uint4* sl = (const uint4*)(g_hb_lo[t & 1] + b0 * UU);
#pragma unroll
            for (int it = 0; it < 2; it++) {
                int u = tid + it * 256;          // 512 units of 8 bf16
                int row = u >> 5, c = (u & 31) << 3;
                *(uint4*)&hs_h[row * HSS + c] = __ldcg(sh + u);
                *(uint4*)&hs_l[row * HSS + c] = __ldcg(sl + u);
            }
        }
        __syncthreads();

        // ---- z = h @ U on tensor cores (3-pass split) ----
        float acc[4] = {0.f, 0.f, 0.f, 0.f};
#pragma unroll
        for (int kc = 0; kc < 16; kc++) {
            uint32_t ah[4], al4[4];
            uint32_t off = aoff + (uint32_t)(kc * 16) * 2;
            ldm_x4(ah,  sh_h + off);
            ldm_x4(al4, sh_l + off);
            mma16816(acc, ah,  bh[kc]);
            mma16816(acc, ah,  bl[kc]);
            mma16816(acc, al4, bh[kc]);
        }
        {
            int r = lane >> 2, cl = wid * 8 + ((lane & 3) << 1);
            *(float2*)&z_s[r * 66 + cl]       = make_float2(acc[0], acc[1]);
            *(float2*)&z_s[(r + 8) * 66 + cl] = make_float2(acc[2], acc[3]);
        }
        __syncthreads();

        // ---- gates: one (b,u) per thread ----
        {
            float zi = z_s[b_l * 66 +      u_l] + xi;
            float zf = z_s[b_l * 66 + 16 + u_l] + xf2;
            float zg = z_s[b_l * 66 + 32 + u_l] + xg;
            float zo = z_s[b_l * 66 + 48 + u_l] + xo;
            float cn = sigm_f(zf) * c_reg + sigm_f(zi) * tanh_f(zg);
            float hn = sigm_f(zo) * tanh_f(cn);
            c_reg = cn;
            __nv_bfloat16 hh, ll; split_bf16(hn, hh, ll);
            g_hb_hi[(t + 1) & 1][gidx] = hh;
            g_hb_lo[(t + 1) & 1][gidx] = ll;
            size_t oidx = ((size_t)(b0 + b_l) * Tlen + t) * UU + u0 + u_l;
            if (outMode == 1) {
                yhi[oidx] = hh; ylo[oidx] = ll;
            } else if (outMode == 2) {
                yfp[oidx] = hn;
            }
            if (t == Tlen - 1) { g_hfin[gidx] = hn; g_cfin[gidx] = cn; }
        }
        group_sync(grp, 16u * (unsigned)(t + 2));   // barrier #(t+1)
    }
}

// ======================= decoder weight combine & dense =======================
__global__ void combine_w_kernel(const float* __restrict__ a, const float* __restrict__ b) {
    int i = blockIdx.x * 256 + threadIdx.x;
    g_wc[i] = a[i] + b[i];
}

__global__ void dense_kernel(const float* __restrict__ h, const float* __restrict__ w,
                             const float* __restrict__ b, float* __restrict__ out) {
    __shared__ float ws[UU * OD];
    for (int i = threadIdx.x; i < UU * OD; i += 256) ws[i] = w[i];
    __syncthreads();
    int idx = blockIdx.x * 256 + threadIdx.x;
    int o   = idx & 7;
    size_t row = idx >> 3;
    float acc = b[o];
    const float* hp = h + row * UU;
#pragma unroll 8
    for (int k = 0; k < UU; k++) acc += hp[k] * ws[k * OD + o];
    out[idx] = acc;
}

// ======================= launch =======================
extern "C" void kernel_launch(void* const* d_in, const int* in_sizes, int n_in,
                              void* d_out, int out_size)
{
    const float* x     = (const float*)d_in[0];
    const float* cnn_w = (const float*)d_in[1];
    const float* cnn_b = (const float*)d_in[2];
    const float* ew0 = (const float*)d_in[3];
    const float* eu0 = (const float*)d_in[4];
    const float* eb0 = (const float*)d_in[5];
    const float* ew1 = (const float*)d_in[6];
    const float* eu1 = (const float*)d_in[7];
    const float* eb1 = (const float*)d_in[8];
    const float* ew2 = (const float*)d_in[9];
    const float* eu2 = (const float*)d_in[10];
    const float* eb2 = (const float*)d_in[11];
    const float* cw  = (const float*)d_in[12];
    const float* cu  = (const float*)d_in[13];
    const float* cb  = (const float*)d_in[14];
    const float* dw  = (const float*)d_in[15];
    const float* db  = (const float*)d_in[16];
    float* out = (float*)d_out;

    __nv_bfloat16 *xch, *xcl, *ah, *al, *wth, *wtl, *uth, *utl, *cwth, *cwtl;
    float *xwp, *hdec, *wc;
    cudaGetSymbolAddress((void**)&xch,  g_xc_hi);
    cudaGetSymbolAddress((void**)&xcl,  g_xc_lo);
    cudaGetSymbolAddress((void**)&ah,   g_a_hi);
    cudaGetSymbolAddress((void**)&al,   g_a_lo);
    cudaGetSymbolAddress((void**)&wth,  g_wt_hi);
    cudaGetSymbolAddress((void**)&wtl,  g_wt_lo);
    cudaGetSymbolAddress((void**)&uth,  g_ut_hi);
    cudaGetSymbolAddress((void**)&utl,  g_ut_lo);
    cudaGetSymbolAddress((void**)&cwth, g_cwt_hi);
    cudaGetSymbolAddress((void**)&cwtl, g_cwt_lo);
    cudaGetSymbolAddress((void**)&xwp,  g_xw);
    cudaGetSymbolAddress((void**)&hdec, g_hdec);
    cudaGetSymbolAddress((void**)&wc,   g_wc);

    const int GEMM_SMEM = 4 * TILE_ELE * 2;
    cudaFuncSetAttribute(mma_gemm<1,1>, cudaFuncAttributeMaxDynamicSharedMemorySize, GEMM_SMEM);
    cudaFuncSetAttribute(mma_gemm<0,0>, cudaFuncAttributeMaxDynamicSharedMemorySize, GEMM_SMEM);

    dim3 scan_grid(16, 16);

    // conv: im2col(split) + HMMA GEMM (bias+ReLU, split-bf16 out)
    im2col_split<<<(int)(((size_t)MTOT * KC) / 256), 256>>>(x);
    wsplit<<<(UU * KC + 255) / 256, 256>>>(cnn_w, cwth, cwtl, KC, UU);
    mma_gemm<1,1><<<dim3(UU / 128, MTOT / 128), 256, GEMM_SMEM>>>(
        xch, xcl, cwth, cwtl, cnn_b, nullptr, ah, al, MTOT, UU, KC);

    // encoder layer 0
    wsplit<<<(UU * G4) / 256, 256>>>(ew0, wth, wtl, UU, G4);
    mma_gemm<0,0><<<dim3(G4 / 128, MTOT / 128), 256, GEMM_SMEM>>>(
        ah, al, wth, wtl, eb0, xwp, nullptr, nullptr, MTOT, G4, UU);
    wsplit<<<(UU * G4) / 256, 256>>>(eu0, uth, utl, UU, G4);
    bar_reset<<<1, 32>>>();
    lstm_scan_mma<<<scan_grid, 256>>>(xwp, nullptr, uth, utl, ah, al, nullptr, TT, 0, 1);

    // encoder layer 1
    wsplit<<<(UU * G4) / 256, 256>>>(ew1, wth, wtl, UU, G4);
    mma_gemm<0,0><<<dim3(G4 / 128, MTOT / 128), 256, GEMM_SMEM>>>(
        ah, al, wth, wtl, eb1, xwp, nullptr, nullptr, MTOT, G4, UU);
    wsplit<<<(UU * G4) / 256, 256>>>(eu1, uth, utl, UU, G4);
    bar_reset<<<1, 32>>>();
    lstm_scan_mma<<<scan_grid, 256>>>(xwp, nullptr, uth, utl, ah, al, nullptr, TT, 0, 1);

    // encoder layer 2 (only final h,c needed)
    wsplit<<<(UU * G4) / 256, 256>>>(ew2, wth, wtl, UU, G4);
    mma_gemm<0,0><<<dim3(G4 / 128, MTOT / 128), 256, GEMM_SMEM>>>(
        ah, al, wth, wtl, eb2, xwp, nullptr, nullptr, MTOT, G4, UU);
    wsplit<<<(UU * G4) / 256, 256>>>(eu2, uth, utl, UU, G4);
    bar_reset<<<1, 32>>>();
    lstm_scan_mma<<<scan_grid, 256>>>(xwp, nullptr, uth, utl, nullptr, nullptr, nullptr, TT, 0, 0);

    // decoder: z = h @ (cell_w + cell_u) + b, 64 steps from (h,c)
    combine_w_kernel<<<(UU * G4) / 256, 256>>>(cw, cu);
    wsplit<<<(UU * G4) / 256, 256>>>(wc, uth, utl, UU, G4);
    bar_reset<<<1, 32>>>();
    lstm_scan_mma<<<scan_grid, 256>>>(nullptr, cb, uth, utl, nullptr, nullptr, hdec, OUTS, 1, 2);

    // dense head
    dense_kernel<<<(BB * OUTS * OD) / 256, 256>>>(hdec, dw, db, out);
}